// round 1
// baseline (speedup 1.0000x reference)
#include <cuda_runtime.h>
#include <cuda_bf16.h>

// Problem dims
#define BB 2
#define TT 2048
#define HH 16
#define DD 64
#define EE 1024   // HH*DD
#define OO 1024

// Scratch (device globals: allocation-free per harness rules)
__device__ float g_q[(size_t)BB * TT * EE];
__device__ float g_k[(size_t)BB * TT * EE];
__device__ float g_v[(size_t)BB * TT * EE];
__device__ float g_mh[(size_t)BB * TT * EE];
__device__ float g_out_scratch[(size_t)BB * TT * OO];
__device__ float g_attn_scratch[(size_t)BB * HH * TT * TT];  // fallback if attn not in d_out

// ---------------------------------------------------------------------------
// Generic tiled GEMM: C[M,N] = alpha * A[M,K] * B (+ bias)
//   TRANSB=1: B element (n,k) at Bm[n*ldb + k]   (x @ W.T case, K-contiguous)
//   TRANSB=0: B element (k,n) at Bm[k*ldb + n]
// Batched over blockIdx.z with offset = (z/zdiv)*s1 + (z%zdiv)*s2 per matrix.
// Tile: 64x64 output, 16-deep K tiles, 256 threads, 4x4 per thread.
// All dims here are multiples of 64/16 so no bounds checks.
// ---------------------------------------------------------------------------
template <int TRANSB>
__global__ __launch_bounds__(256) void gemm64(
    const float* __restrict__ A, int lda, int zdiv,
    long long sA1, long long sA2,
    const float* __restrict__ Bm, int ldb,
    long long sB1, long long sB2,
    float* __restrict__ C, int ldc,
    long long sC1, long long sC2,
    int K, float alpha, const float* __restrict__ bias)
{
    __shared__ float As[16][64];
    __shared__ float Bs[16][64];

    const int z = blockIdx.z;
    const int z1 = z / zdiv, z2 = z % zdiv;
    A  += (long long)z1 * sA1 + (long long)z2 * sA2;
    Bm += (long long)z1 * sB1 + (long long)z2 * sB2;
    C  += (long long)z1 * sC1 + (long long)z2 * sC2;

    const int m0 = blockIdx.y * 64;
    const int n0 = blockIdx.x * 64;

    const int tid = threadIdx.x;
    const int ty = tid >> 4;   // 0..15
    const int tx = tid & 15;   // 0..15

    float c[4][4];
#pragma unroll
    for (int i = 0; i < 4; i++)
#pragma unroll
        for (int j = 0; j < 4; j++) c[i][j] = 0.f;

    // A-load indices: row r = tid/4 (0..63), quad c4 = tid%4 over k
    const int ar = tid >> 2;
    const int ac4 = tid & 3;

    for (int kb = 0; kb < K; kb += 16) {
        // Load A tile -> As[k][m] (transposed for float4 reads along m)
        {
            float4 a = *(const float4*)&A[(long long)(m0 + ar) * lda + kb + ac4 * 4];
            As[ac4 * 4 + 0][ar] = a.x;
            As[ac4 * 4 + 1][ar] = a.y;
            As[ac4 * 4 + 2][ar] = a.z;
            As[ac4 * 4 + 3][ar] = a.w;
        }
        // Load B tile -> Bs[k][n]
        if (TRANSB) {
            const int bn = tid >> 2;
            const int bc4 = tid & 3;
            float4 b = *(const float4*)&Bm[(long long)(n0 + bn) * ldb + kb + bc4 * 4];
            Bs[bc4 * 4 + 0][bn] = b.x;
            Bs[bc4 * 4 + 1][bn] = b.y;
            Bs[bc4 * 4 + 2][bn] = b.z;
            Bs[bc4 * 4 + 3][bn] = b.w;
        } else {
            const int bk = tid >> 4;   // 0..15
            const int bc = tid & 15;   // 0..15
            float4 b = *(const float4*)&Bm[(long long)(kb + bk) * ldb + n0 + bc * 4];
            *(float4*)&Bs[bk][bc * 4] = b;
        }
        __syncthreads();

#pragma unroll
        for (int kk = 0; kk < 16; kk++) {
            float4 av = *(const float4*)&As[kk][ty * 4];
            float4 bv = *(const float4*)&Bs[kk][tx * 4];
            float a0 = av.x, a1 = av.y, a2 = av.z, a3 = av.w;
            float b0 = bv.x, b1 = bv.y, b2 = bv.z, b3 = bv.w;
            c[0][0] += a0 * b0; c[0][1] += a0 * b1; c[0][2] += a0 * b2; c[0][3] += a0 * b3;
            c[1][0] += a1 * b0; c[1][1] += a1 * b1; c[1][2] += a1 * b2; c[1][3] += a1 * b3;
            c[2][0] += a2 * b0; c[2][1] += a2 * b1; c[2][2] += a2 * b2; c[2][3] += a2 * b3;
            c[3][0] += a3 * b0; c[3][1] += a3 * b1; c[3][2] += a3 * b2; c[3][3] += a3 * b3;
        }
        __syncthreads();
    }

    float4 bb = make_float4(0.f, 0.f, 0.f, 0.f);
    if (bias) bb = *(const float4*)&bias[n0 + tx * 4];

#pragma unroll
    for (int i = 0; i < 4; i++) {
        float4 r;
        r.x = c[i][0] * alpha + bb.x;
        r.y = c[i][1] * alpha + bb.y;
        r.z = c[i][2] * alpha + bb.z;
        r.w = c[i][3] * alpha + bb.w;
        *(float4*)&C[(long long)(m0 + ty * 4 + i) * ldc + n0 + tx * 4] = r;
    }
}

// ---------------------------------------------------------------------------
// Row softmax, in place. One block (256 threads) per row of length TT=2048.
// ---------------------------------------------------------------------------
__global__ __launch_bounds__(256) void softmax_rows(float* __restrict__ attn)
{
    __shared__ float red[256];
    const long long row = blockIdx.x;
    float4* p4 = (float4*)(attn + row * (long long)TT);
    const int t = threadIdx.x;

    float4 a = p4[t];
    float4 b = p4[t + 256];

    float m = fmaxf(fmaxf(fmaxf(a.x, a.y), fmaxf(a.z, a.w)),
                    fmaxf(fmaxf(b.x, b.y), fmaxf(b.z, b.w)));
    red[t] = m;
    __syncthreads();
#pragma unroll
    for (int s = 128; s > 0; s >>= 1) {
        if (t < s) red[t] = fmaxf(red[t], red[t + s]);
        __syncthreads();
    }
    m = red[0];
    __syncthreads();

    a.x = __expf(a.x - m); a.y = __expf(a.y - m);
    a.z = __expf(a.z - m); a.w = __expf(a.w - m);
    b.x = __expf(b.x - m); b.y = __expf(b.y - m);
    b.z = __expf(b.z - m); b.w = __expf(b.w - m);

    float sum = a.x + a.y + a.z + a.w + b.x + b.y + b.z + b.w;
    red[t] = sum;
    __syncthreads();
#pragma unroll
    for (int s = 128; s > 0; s >>= 1) {
        if (t < s) red[t] += red[t + s];
        __syncthreads();
    }
    const float inv = 1.f / red[0];

    a.x *= inv; a.y *= inv; a.z *= inv; a.w *= inv;
    b.x *= inv; b.y *= inv; b.z *= inv; b.w *= inv;
    p4[t] = a;
    p4[t + 256] = b;
}

// ---------------------------------------------------------------------------
// Launch
// Inputs (metadata order): query, key, value, Wq, Wk, Wv, proj_kernel, proj_bias
// Output: [ out (B*T*O) | attn (B*H*T*T) ]  (fallback if out_size differs)
// ---------------------------------------------------------------------------
extern "C" void kernel_launch(void* const* d_in, const int* in_sizes, int n_in,
                              void* d_out, int out_size)
{
    const float* query = (const float*)d_in[0];
    const float* key   = (const float*)d_in[1];
    const float* value = (const float*)d_in[2];
    const float* Wq    = (const float*)d_in[3];
    const float* Wk    = (const float*)d_in[4];
    const float* Wv    = (const float*)d_in[5];
    const float* pk    = (const float*)d_in[6];
    const float* pb    = (const float*)d_in[7];

    float *qp, *kp, *vp, *mhp, *outs, *attns;
    cudaGetSymbolAddress((void**)&qp,    g_q);
    cudaGetSymbolAddress((void**)&kp,    g_k);
    cudaGetSymbolAddress((void**)&vp,    g_v);
    cudaGetSymbolAddress((void**)&mhp,   g_mh);
    cudaGetSymbolAddress((void**)&outs,  g_out_scratch);
    cudaGetSymbolAddress((void**)&attns, g_attn_scratch);

    const long long outN  = (long long)BB * TT * OO;                // 4194304
    const long long attnN = (long long)BB * HH * TT * TT;           // 134217728

    float* outP  = (float*)d_out;
    float* attnP;
    if ((long long)out_size >= outN + attnN) {
        attnP = outP + outN;                 // concatenated outputs
    } else if ((long long)out_size == attnN) {
        attnP = (float*)d_out;               // attn-only output
        outP  = outs;
    } else {
        attnP = attns;                       // out-only output
    }

    // 1) Q/K/V projections: [B*T, E] = X[B*T, E] @ W.T   (TRANSB=1)
    {
        dim3 grid(EE / 64, (BB * TT) / 64, 1);
        gemm64<1><<<grid, 256>>>(query, EE, 1, 0, 0, Wq, EE, 0, 0,
                                 qp, EE, 0, 0, EE, 1.f, nullptr);
        gemm64<1><<<grid, 256>>>(key,   EE, 1, 0, 0, Wk, EE, 0, 0,
                                 kp, EE, 0, 0, EE, 1.f, nullptr);
        gemm64<1><<<grid, 256>>>(value, EE, 1, 0, 0, Wv, EE, 0, 0,
                                 vp, EE, 0, 0, EE, 1.f, nullptr);
    }

    // 2) logits[b,h,n,m] = (1/sqrt(D)) * q[b,n,h,:] . k[b,m,h,:]
    //    batched over z = b*H + h
    {
        dim3 grid(TT / 64, TT / 64, BB * HH);
        gemm64<1><<<grid, 256>>>(
            qp, HH * DD, HH, (long long)TT * EE, DD,
            kp, HH * DD,     (long long)TT * EE, DD,
            attnP, TT,       (long long)HH * TT * TT, (long long)TT * TT,
            DD, 0.125f, nullptr);
    }

    // 3) softmax rows (in place on attn output)
    softmax_rows<<<BB * HH * TT, 256>>>(attnP);

    // 4) mh[b,n,h,d] = sum_m attn[b,h,n,m] * v[b,m,h,d]   (TRANSB=0)
    {
        dim3 grid(DD / 64, TT / 64, BB * HH);
        gemm64<0><<<grid, 256>>>(
            attnP, TT, HH, (long long)HH * TT * TT, (long long)TT * TT,
            vp, HH * DD,   (long long)TT * EE, DD,
            mhp, HH * DD,  (long long)TT * EE, DD,
            TT, 1.f, nullptr);
    }

    // 5) out[b,n,o] = mh[b,n,:] @ proj_kernel[(h*D+d), o] + bias[o]
    {
        dim3 grid(OO / 64, (BB * TT) / 64, 1);
        gemm64<0><<<grid, 256>>>(mhp, EE, 1, 0, 0, pk, OO, 0, 0,
                                 outP, OO, 0, 0, EE, 1.f, pb);
    }
}

// round 2
// speedup vs baseline: 1.1747x; 1.1747x over previous
#include <cuda_runtime.h>
#include <cuda_bf16.h>

// Problem dims
#define BB 2
#define TT 2048
#define HH 16
#define DD 64
#define EE 1024   // HH*DD
#define OO 1024

// Scratch (device globals: allocation-free per harness rules)
__device__ float g_q[(size_t)BB * TT * EE];
__device__ float g_k[(size_t)BB * TT * EE];
__device__ float g_v[(size_t)BB * TT * EE];
__device__ float g_mh[(size_t)BB * TT * EE];
__device__ float g_out_scratch[(size_t)BB * TT * OO];
__device__ float g_attn_scratch[(size_t)BB * HH * TT * TT];  // fallback if attn not in d_out

// ---------------------------------------------------------------------------
// 128x128 tiled GEMM, 256 threads, 8x8 per thread, K-step 16.
// C[M,N] = alpha * A[M,K] * B (+ bias)
//   TRANSB=1: B element (n,k) at Bm[n*ldb + k]
//   TRANSB=0: B element (k,n) at Bm[k*ldb + n]
// Batched over blockIdx.z: offset = (z/zdiv)*s1 + (z%zdiv)*s2.
// All dims multiples of 128/16 at our shapes -> no bounds checks.
// ---------------------------------------------------------------------------
template <int TRANSB>
__global__ __launch_bounds__(256) void gemm128(
    const float* __restrict__ A, int lda, int zdiv,
    long long sA1, long long sA2,
    const float* __restrict__ Bm, int ldb,
    long long sB1, long long sB2,
    float* __restrict__ C, int ldc,
    long long sC1, long long sC2,
    int K, float alpha, const float* __restrict__ bias)
{
    __shared__ float As[16][128];
    __shared__ float Bs[16][128];

    const int z = blockIdx.z;
    const int z1 = z / zdiv, z2 = z % zdiv;
    A  += (long long)z1 * sA1 + (long long)z2 * sA2;
    Bm += (long long)z1 * sB1 + (long long)z2 * sB2;
    C  += (long long)z1 * sC1 + (long long)z2 * sC2;

    const int m0 = blockIdx.y * 128;
    const int n0 = blockIdx.x * 128;

    const int tid = threadIdx.x;
    const int ty = tid >> 4;   // 0..15
    const int tx = tid & 15;   // 0..15

    float acc[8][8];
#pragma unroll
    for (int i = 0; i < 8; i++)
#pragma unroll
        for (int j = 0; j < 8; j++) acc[i][j] = 0.f;

    // load indices: one 128-row tile, 16-deep k. 2 float4 per thread per matrix (transposed case)
    const int lr = tid >> 1;         // 0..127
    const int lk = (tid & 1) * 8;    // 0 or 8
    // TRANSB=0 B loads: 2 float4 per thread, contiguous along n
    const int bk0 = tid >> 5;        // 0..7
    const int bn0 = (tid & 31) * 4;  // 0..124

    for (int kb = 0; kb < K; kb += 16) {
        // A tile -> As[k][m]
        {
            const float* ap = &A[(long long)(m0 + lr) * lda + kb + lk];
            float4 a0 = *(const float4*)(ap);
            float4 a1 = *(const float4*)(ap + 4);
            As[lk + 0][lr] = a0.x; As[lk + 1][lr] = a0.y;
            As[lk + 2][lr] = a0.z; As[lk + 3][lr] = a0.w;
            As[lk + 4][lr] = a1.x; As[lk + 5][lr] = a1.y;
            As[lk + 6][lr] = a1.z; As[lk + 7][lr] = a1.w;
        }
        // B tile -> Bs[k][n]
        if (TRANSB) {
            const float* bp = &Bm[(long long)(n0 + lr) * ldb + kb + lk];
            float4 b0 = *(const float4*)(bp);
            float4 b1 = *(const float4*)(bp + 4);
            Bs[lk + 0][lr] = b0.x; Bs[lk + 1][lr] = b0.y;
            Bs[lk + 2][lr] = b0.z; Bs[lk + 3][lr] = b0.w;
            Bs[lk + 4][lr] = b1.x; Bs[lk + 5][lr] = b1.y;
            Bs[lk + 6][lr] = b1.z; Bs[lk + 7][lr] = b1.w;
        } else {
            *(float4*)&Bs[bk0][bn0]     = *(const float4*)&Bm[(long long)(kb + bk0) * ldb + n0 + bn0];
            *(float4*)&Bs[bk0 + 8][bn0] = *(const float4*)&Bm[(long long)(kb + bk0 + 8) * ldb + n0 + bn0];
        }
        __syncthreads();

#pragma unroll
        for (int kk = 0; kk < 16; kk++) {
            float4 a0 = *(const float4*)&As[kk][ty * 4];
            float4 a1 = *(const float4*)&As[kk][ty * 4 + 64];
            float4 b0 = *(const float4*)&Bs[kk][tx * 4];
            float4 b1 = *(const float4*)&Bs[kk][tx * 4 + 64];
            float ar[8] = {a0.x, a0.y, a0.z, a0.w, a1.x, a1.y, a1.z, a1.w};
            float br[8] = {b0.x, b0.y, b0.z, b0.w, b1.x, b1.y, b1.z, b1.w};
#pragma unroll
            for (int i = 0; i < 8; i++)
#pragma unroll
                for (int j = 0; j < 8; j++)
                    acc[i][j] += ar[i] * br[j];
        }
        __syncthreads();
    }

    float4 bbl = make_float4(0.f, 0.f, 0.f, 0.f);
    float4 bbh = make_float4(0.f, 0.f, 0.f, 0.f);
    if (bias) {
        bbl = *(const float4*)&bias[n0 + tx * 4];
        bbh = *(const float4*)&bias[n0 + tx * 4 + 64];
    }

#pragma unroll
    for (int i = 0; i < 8; i++) {
        const int row = m0 + (i < 4 ? ty * 4 + i : 64 + ty * 4 + (i - 4));
        float4 r0, r1;
        r0.x = acc[i][0] * alpha + bbl.x;
        r0.y = acc[i][1] * alpha + bbl.y;
        r0.z = acc[i][2] * alpha + bbl.z;
        r0.w = acc[i][3] * alpha + bbl.w;
        r1.x = acc[i][4] * alpha + bbh.x;
        r1.y = acc[i][5] * alpha + bbh.y;
        r1.z = acc[i][6] * alpha + bbh.z;
        r1.w = acc[i][7] * alpha + bbh.w;
        *(float4*)&C[(long long)row * ldc + n0 + tx * 4]      = r0;
        *(float4*)&C[(long long)row * ldc + n0 + tx * 4 + 64] = r1;
    }
}

// ---------------------------------------------------------------------------
// 128x64 tiled GEMM (for attn @ V, N = D = 64), TRANSB=0 only.
// 256 threads, 8x4 per thread, K-step 16.
// ---------------------------------------------------------------------------
__global__ __launch_bounds__(256) void gemm_av(
    const float* __restrict__ A, int lda, int zdiv,
    long long sA1, long long sA2,
    const float* __restrict__ Bm, int ldb,
    long long sB1, long long sB2,
    float* __restrict__ C, int ldc,
    long long sC1, long long sC2,
    int K)
{
    __shared__ float As[16][128];
    __shared__ float Bs[16][64];

    const int z = blockIdx.z;
    const int z1 = z / zdiv, z2 = z % zdiv;
    A  += (long long)z1 * sA1 + (long long)z2 * sA2;
    Bm += (long long)z1 * sB1 + (long long)z2 * sB2;
    C  += (long long)z1 * sC1 + (long long)z2 * sC2;

    const int m0 = blockIdx.y * 128;

    const int tid = threadIdx.x;
    const int ty = tid >> 4;   // 0..15
    const int tx = tid & 15;   // 0..15

    float acc[8][4];
#pragma unroll
    for (int i = 0; i < 8; i++)
#pragma unroll
        for (int j = 0; j < 4; j++) acc[i][j] = 0.f;

    const int lr = tid >> 1;
    const int lk = (tid & 1) * 8;
    const int bk = tid >> 4;          // 0..15
    const int bn = (tid & 15) * 4;    // 0..60

    for (int kb = 0; kb < K; kb += 16) {
        {
            const float* ap = &A[(long long)(m0 + lr) * lda + kb + lk];
            float4 a0 = *(const float4*)(ap);
            float4 a1 = *(const float4*)(ap + 4);
            As[lk + 0][lr] = a0.x; As[lk + 1][lr] = a0.y;
            As[lk + 2][lr] = a0.z; As[lk + 3][lr] = a0.w;
            As[lk + 4][lr] = a1.x; As[lk + 5][lr] = a1.y;
            As[lk + 6][lr] = a1.z; As[lk + 7][lr] = a1.w;
        }
        *(float4*)&Bs[bk][bn] = *(const float4*)&Bm[(long long)(kb + bk) * ldb + bn];
        __syncthreads();

#pragma unroll
        for (int kk = 0; kk < 16; kk++) {
            float4 a0 = *(const float4*)&As[kk][ty * 4];
            float4 a1 = *(const float4*)&As[kk][ty * 4 + 64];
            float4 b0 = *(const float4*)&Bs[kk][tx * 4];
            float ar[8] = {a0.x, a0.y, a0.z, a0.w, a1.x, a1.y, a1.z, a1.w};
            float br[4] = {b0.x, b0.y, b0.z, b0.w};
#pragma unroll
            for (int i = 0; i < 8; i++)
#pragma unroll
                for (int j = 0; j < 4; j++)
                    acc[i][j] += ar[i] * br[j];
        }
        __syncthreads();
    }

#pragma unroll
    for (int i = 0; i < 8; i++) {
        const int row = m0 + (i < 4 ? ty * 4 + i : 64 + ty * 4 + (i - 4));
        float4 r;
        r.x = acc[i][0]; r.y = acc[i][1]; r.z = acc[i][2]; r.w = acc[i][3];
        *(float4*)&C[(long long)row * ldc + tx * 4] = r;
    }
}

// ---------------------------------------------------------------------------
// Row softmax, in place. One block (256 threads) per row of length TT=2048.
// ---------------------------------------------------------------------------
__global__ __launch_bounds__(256) void softmax_rows(float* __restrict__ attn)
{
    __shared__ float red[256];
    const long long row = blockIdx.x;
    float4* p4 = (float4*)(attn + row * (long long)TT);
    const int t = threadIdx.x;

    float4 a = p4[t];
    float4 b = p4[t + 256];

    float m = fmaxf(fmaxf(fmaxf(a.x, a.y), fmaxf(a.z, a.w)),
                    fmaxf(fmaxf(b.x, b.y), fmaxf(b.z, b.w)));
    red[t] = m;
    __syncthreads();
#pragma unroll
    for (int s = 128; s > 0; s >>= 1) {
        if (t < s) red[t] = fmaxf(red[t], red[t + s]);
        __syncthreads();
    }
    m = red[0];
    __syncthreads();

    a.x = __expf(a.x - m); a.y = __expf(a.y - m);
    a.z = __expf(a.z - m); a.w = __expf(a.w - m);
    b.x = __expf(b.x - m); b.y = __expf(b.y - m);
    b.z = __expf(b.z - m); b.w = __expf(b.w - m);

    float sum = a.x + a.y + a.z + a.w + b.x + b.y + b.z + b.w;
    red[t] = sum;
    __syncthreads();
#pragma unroll
    for (int s = 128; s > 0; s >>= 1) {
        if (t < s) red[t] += red[t + s];
        __syncthreads();
    }
    const float inv = 1.f / red[0];

    a.x *= inv; a.y *= inv; a.z *= inv; a.w *= inv;
    b.x *= inv; b.y *= inv; b.z *= inv; b.w *= inv;
    p4[t] = a;
    p4[t + 256] = b;
}

// ---------------------------------------------------------------------------
// Launch
// Inputs (metadata order): query, key, value, Wq, Wk, Wv, proj_kernel, proj_bias
// Output: [ out (B*T*O) | attn (B*H*T*T) ]  (fallback if out_size differs)
// ---------------------------------------------------------------------------
extern "C" void kernel_launch(void* const* d_in, const int* in_sizes, int n_in,
                              void* d_out, int out_size)
{
    const float* query = (const float*)d_in[0];
    const float* key   = (const float*)d_in[1];
    const float* value = (const float*)d_in[2];
    const float* Wq    = (const float*)d_in[3];
    const float* Wk    = (const float*)d_in[4];
    const float* Wv    = (const float*)d_in[5];
    const float* pk    = (const float*)d_in[6];
    const float* pb    = (const float*)d_in[7];

    float *qp, *kp, *vp, *mhp, *outs, *attns;
    cudaGetSymbolAddress((void**)&qp,    g_q);
    cudaGetSymbolAddress((void**)&kp,    g_k);
    cudaGetSymbolAddress((void**)&vp,    g_v);
    cudaGetSymbolAddress((void**)&mhp,   g_mh);
    cudaGetSymbolAddress((void**)&outs,  g_out_scratch);
    cudaGetSymbolAddress((void**)&attns, g_attn_scratch);

    const long long outN  = (long long)BB * TT * OO;                // 4194304
    const long long attnN = (long long)BB * HH * TT * TT;           // 134217728

    float* outP  = (float*)d_out;
    float* attnP;
    if ((long long)out_size >= outN + attnN) {
        attnP = outP + outN;                 // concatenated outputs
    } else if ((long long)out_size == attnN) {
        attnP = (float*)d_out;               // attn-only output
        outP  = outs;
    } else {
        attnP = attns;                       // out-only output
    }

    // 1) Q/K/V projections: [B*T, E] = X[B*T, E] @ W.T   (TRANSB=1)
    {
        dim3 grid(EE / 128, (BB * TT) / 128, 1);
        gemm128<1><<<grid, 256>>>(query, EE, 1, 0, 0, Wq, EE, 0, 0,
                                  qp, EE, 0, 0, EE, 1.f, nullptr);
        gemm128<1><<<grid, 256>>>(key,   EE, 1, 0, 0, Wk, EE, 0, 0,
                                  kp, EE, 0, 0, EE, 1.f, nullptr);
        gemm128<1><<<grid, 256>>>(value, EE, 1, 0, 0, Wv, EE, 0, 0,
                                  vp, EE, 0, 0, EE, 1.f, nullptr);
    }

    // 2) logits[b,h,n,m] = (1/sqrt(D)) * q[b,n,h,:] . k[b,m,h,:]
    {
        dim3 grid(TT / 128, TT / 128, BB * HH);
        gemm128<1><<<grid, 256>>>(
            qp, HH * DD, HH, (long long)TT * EE, DD,
            kp, HH * DD,     (long long)TT * EE, DD,
            attnP, TT,       (long long)HH * TT * TT, (long long)TT * TT,
            DD, 0.125f, nullptr);
    }

    // 3) softmax rows (in place on attn output)
    softmax_rows<<<BB * HH * TT, 256>>>(attnP);

    // 4) mh[b,n,h,d] = sum_m attn[b,h,n,m] * v[b,m,h,d]
    {
        dim3 grid(1, TT / 128, BB * HH);
        gemm_av<<<grid, 256>>>(
            attnP, TT, HH, (long long)HH * TT * TT, (long long)TT * TT,
            vp, HH * DD,   (long long)TT * EE, DD,
            mhp, HH * DD,  (long long)TT * EE, DD,
            TT);
    }

    // 5) out[b,n,o] = mh[b,n,:] @ proj_kernel[(h*D+d), o] + bias[o]
    {
        dim3 grid(OO / 128, (BB * TT) / 128, 1);
        gemm128<0><<<grid, 256>>>(mhp, EE, 1, 0, 0, pk, OO, 0, 0,
                                  outP, OO, 0, 0, EE, 1.f, pb);
    }
}

// round 3
// speedup vs baseline: 1.2808x; 1.0903x over previous
#include <cuda_runtime.h>
#include <cuda_bf16.h>

// Problem dims
#define BB 2
#define TT 2048
#define HH 16
#define DD 64
#define EE 1024   // HH*DD
#define OO 1024

// Scratch (device globals: allocation-free per harness rules)
__device__ float g_q[(size_t)BB * TT * EE];
__device__ float g_k[(size_t)BB * TT * EE];
__device__ float g_v[(size_t)BB * TT * EE];
__device__ float g_mh[(size_t)BB * TT * EE];
__device__ float g_out_scratch[(size_t)BB * TT * OO];
__device__ float g_attn_scratch[(size_t)BB * HH * TT * TT];  // fallback if attn not in d_out

// ---------------------------------------------------------------------------
// f32x2 packed math helpers (Blackwell sm_103a)
// ---------------------------------------------------------------------------
__device__ __forceinline__ unsigned long long pack2_dup(float x) {
    unsigned long long r;
    asm("mov.b64 %0, {%1, %1};" : "=l"(r) : "f"(x));
    return r;
}
__device__ __forceinline__ void ffma2(unsigned long long& d,
                                      unsigned long long a,
                                      unsigned long long b) {
    asm("fma.rn.f32x2 %0, %1, %2, %3;" : "=l"(d) : "l"(a), "l"(b), "l"(d));
}
__device__ __forceinline__ float2 unpack2(unsigned long long v) {
    float lo, hi;
    asm("mov.b64 {%0, %1}, %2;" : "=f"(lo), "=f"(hi) : "l"(v));
    return make_float2(lo, hi);
}

// ---------------------------------------------------------------------------
// 128x128 tiled GEMM, 256 threads, 8x8 per thread (f32x2 packed), K-step 16.
// C[M,N] = alpha * A[M,K] * B (+ bias)
//   TRANSB=1: B element (n,k) at Bm[n*ldb + k]
//   TRANSB=0: B element (k,n) at Bm[k*ldb + n]
// Batched over blockIdx.z: offset = (z/zdiv)*s1 + (z%zdiv)*s2.
// ---------------------------------------------------------------------------
template <int TRANSB>
__global__ __launch_bounds__(256) void gemm128(
    const float* __restrict__ A, int lda, int zdiv,
    long long sA1, long long sA2,
    const float* __restrict__ Bm, int ldb,
    long long sB1, long long sB2,
    float* __restrict__ C, int ldc,
    long long sC1, long long sC2,
    int K, float alpha, const float* __restrict__ bias)
{
    __shared__ float As[16][128];
    __shared__ float Bs[16][128];

    const int z = blockIdx.z;
    const int z1 = z / zdiv, z2 = z % zdiv;
    A  += (long long)z1 * sA1 + (long long)z2 * sA2;
    Bm += (long long)z1 * sB1 + (long long)z2 * sB2;
    C  += (long long)z1 * sC1 + (long long)z2 * sC2;

    const int m0 = blockIdx.y * 128;
    const int n0 = blockIdx.x * 128;

    const int tid = threadIdx.x;
    const int ty = tid >> 4;   // 0..15
    const int tx = tid & 15;   // 0..15

    // acc[i][jp] : i = 8 rows, jp = 4 packed col-pairs (cols: jp<2 -> tx*4+jp*2, jp>=2 -> +64)
    unsigned long long acc[8][4];
#pragma unroll
    for (int i = 0; i < 8; i++)
#pragma unroll
        for (int j = 0; j < 4; j++) acc[i][j] = 0ull;

    const int lr = tid >> 1;         // 0..127
    const int lk = (tid & 1) * 8;    // 0 or 8
    const int bk0 = tid >> 5;        // 0..7
    const int bn0 = (tid & 31) * 4;  // 0..124

    for (int kb = 0; kb < K; kb += 16) {
        // A tile -> As[k][m]
        {
            const float* ap = &A[(long long)(m0 + lr) * lda + kb + lk];
            float4 a0 = *(const float4*)(ap);
            float4 a1 = *(const float4*)(ap + 4);
            As[lk + 0][lr] = a0.x; As[lk + 1][lr] = a0.y;
            As[lk + 2][lr] = a0.z; As[lk + 3][lr] = a0.w;
            As[lk + 4][lr] = a1.x; As[lk + 5][lr] = a1.y;
            As[lk + 6][lr] = a1.z; As[lk + 7][lr] = a1.w;
        }
        // B tile -> Bs[k][n]
        if (TRANSB) {
            const float* bp = &Bm[(long long)(n0 + lr) * ldb + kb + lk];
            float4 b0 = *(const float4*)(bp);
            float4 b1 = *(const float4*)(bp + 4);
            Bs[lk + 0][lr] = b0.x; Bs[lk + 1][lr] = b0.y;
            Bs[lk + 2][lr] = b0.z; Bs[lk + 3][lr] = b0.w;
            Bs[lk + 4][lr] = b1.x; Bs[lk + 5][lr] = b1.y;
            Bs[lk + 6][lr] = b1.z; Bs[lk + 7][lr] = b1.w;
        } else {
            *(float4*)&Bs[bk0][bn0]     = *(const float4*)&Bm[(long long)(kb + bk0) * ldb + n0 + bn0];
            *(float4*)&Bs[bk0 + 8][bn0] = *(const float4*)&Bm[(long long)(kb + bk0 + 8) * ldb + n0 + bn0];
        }
        __syncthreads();

#pragma unroll
        for (int kk = 0; kk < 16; kk++) {
            float4 a0 = *(const float4*)&As[kk][ty * 4];
            float4 a1 = *(const float4*)&As[kk][ty * 4 + 64];
            // B pairs directly as 64-bit lanes (LDS.128 each)
            ulonglong2 b0 = *(const ulonglong2*)&Bs[kk][tx * 4];
            ulonglong2 b1 = *(const ulonglong2*)&Bs[kk][tx * 4 + 64];
            unsigned long long bp[4] = {b0.x, b0.y, b1.x, b1.y};
            unsigned long long ap[8] = {
                pack2_dup(a0.x), pack2_dup(a0.y), pack2_dup(a0.z), pack2_dup(a0.w),
                pack2_dup(a1.x), pack2_dup(a1.y), pack2_dup(a1.z), pack2_dup(a1.w)};
#pragma unroll
            for (int i = 0; i < 8; i++)
#pragma unroll
                for (int j = 0; j < 4; j++)
                    ffma2(acc[i][j], ap[i], bp[j]);
        }
        __syncthreads();
    }

    float4 bbl = make_float4(0.f, 0.f, 0.f, 0.f);
    float4 bbh = make_float4(0.f, 0.f, 0.f, 0.f);
    if (bias) {
        bbl = *(const float4*)&bias[n0 + tx * 4];
        bbh = *(const float4*)&bias[n0 + tx * 4 + 64];
    }

#pragma unroll
    for (int i = 0; i < 8; i++) {
        const int row = m0 + (i < 4 ? ty * 4 + i : 64 + ty * 4 + (i - 4));
        float2 c0 = unpack2(acc[i][0]);
        float2 c1 = unpack2(acc[i][1]);
        float2 c2 = unpack2(acc[i][2]);
        float2 c3 = unpack2(acc[i][3]);
        float4 r0, r1;
        r0.x = c0.x * alpha + bbl.x;
        r0.y = c0.y * alpha + bbl.y;
        r0.z = c1.x * alpha + bbl.z;
        r0.w = c1.y * alpha + bbl.w;
        r1.x = c2.x * alpha + bbh.x;
        r1.y = c2.y * alpha + bbh.y;
        r1.z = c3.x * alpha + bbh.z;
        r1.w = c3.y * alpha + bbh.w;
        *(float4*)&C[(long long)row * ldc + n0 + tx * 4]      = r0;
        *(float4*)&C[(long long)row * ldc + n0 + tx * 4 + 64] = r1;
    }
}

// ---------------------------------------------------------------------------
// 128x64 tiled GEMM (for attn @ V, N = D = 64), TRANSB=0 only.
// 256 threads, 8x4 per thread (f32x2 packed), K-step 16.
// ---------------------------------------------------------------------------
__global__ __launch_bounds__(256) void gemm_av(
    const float* __restrict__ A, int lda, int zdiv,
    long long sA1, long long sA2,
    const float* __restrict__ Bm, int ldb,
    long long sB1, long long sB2,
    float* __restrict__ C, int ldc,
    long long sC1, long long sC2,
    int K)
{
    __shared__ float As[16][128];
    __shared__ float Bs[16][64];

    const int z = blockIdx.z;
    const int z1 = z / zdiv, z2 = z % zdiv;
    A  += (long long)z1 * sA1 + (long long)z2 * sA2;
    Bm += (long long)z1 * sB1 + (long long)z2 * sB2;
    C  += (long long)z1 * sC1 + (long long)z2 * sC2;

    const int m0 = blockIdx.y * 128;

    const int tid = threadIdx.x;
    const int ty = tid >> 4;   // 0..15
    const int tx = tid & 15;   // 0..15

    unsigned long long acc[8][2];
#pragma unroll
    for (int i = 0; i < 8; i++) { acc[i][0] = 0ull; acc[i][1] = 0ull; }

    const int lr = tid >> 1;
    const int lk = (tid & 1) * 8;
    const int bk = tid >> 4;          // 0..15
    const int bn = (tid & 15) * 4;    // 0..60

    for (int kb = 0; kb < K; kb += 16) {
        {
            const float* ap = &A[(long long)(m0 + lr) * lda + kb + lk];
            float4 a0 = *(const float4*)(ap);
            float4 a1 = *(const float4*)(ap + 4);
            As[lk + 0][lr] = a0.x; As[lk + 1][lr] = a0.y;
            As[lk + 2][lr] = a0.z; As[lk + 3][lr] = a0.w;
            As[lk + 4][lr] = a1.x; As[lk + 5][lr] = a1.y;
            As[lk + 6][lr] = a1.z; As[lk + 7][lr] = a1.w;
        }
        *(float4*)&Bs[bk][bn] = *(const float4*)&Bm[(long long)(kb + bk) * ldb + bn];
        __syncthreads();

#pragma unroll
        for (int kk = 0; kk < 16; kk++) {
            float4 a0 = *(const float4*)&As[kk][ty * 4];
            float4 a1 = *(const float4*)&As[kk][ty * 4 + 64];
            ulonglong2 b0 = *(const ulonglong2*)&Bs[kk][tx * 4];
            unsigned long long bp[2] = {b0.x, b0.y};
            unsigned long long ap[8] = {
                pack2_dup(a0.x), pack2_dup(a0.y), pack2_dup(a0.z), pack2_dup(a0.w),
                pack2_dup(a1.x), pack2_dup(a1.y), pack2_dup(a1.z), pack2_dup(a1.w)};
#pragma unroll
            for (int i = 0; i < 8; i++) {
                ffma2(acc[i][0], ap[i], bp[0]);
                ffma2(acc[i][1], ap[i], bp[1]);
            }
        }
        __syncthreads();
    }

#pragma unroll
    for (int i = 0; i < 8; i++) {
        const int row = m0 + (i < 4 ? ty * 4 + i : 64 + ty * 4 + (i - 4));
        float2 c0 = unpack2(acc[i][0]);
        float2 c1 = unpack2(acc[i][1]);
        float4 r;
        r.x = c0.x; r.y = c0.y; r.z = c1.x; r.w = c1.y;
        *(float4*)&C[(long long)row * ldc + tx * 4] = r;
    }
}

// ---------------------------------------------------------------------------
// Row softmax, in place. One block (256 threads) per row of length TT=2048.
// ---------------------------------------------------------------------------
__global__ __launch_bounds__(256) void softmax_rows(float* __restrict__ attn)
{
    __shared__ float red[256];
    const long long row = blockIdx.x;
    float4* p4 = (float4*)(attn + row * (long long)TT);
    const int t = threadIdx.x;

    float4 a = p4[t];
    float4 b = p4[t + 256];

    float m = fmaxf(fmaxf(fmaxf(a.x, a.y), fmaxf(a.z, a.w)),
                    fmaxf(fmaxf(b.x, b.y), fmaxf(b.z, b.w)));
    red[t] = m;
    __syncthreads();
#pragma unroll
    for (int s = 128; s > 0; s >>= 1) {
        if (t < s) red[t] = fmaxf(red[t], red[t + s]);
        __syncthreads();
    }
    m = red[0];
    __syncthreads();

    a.x = __expf(a.x - m); a.y = __expf(a.y - m);
    a.z = __expf(a.z - m); a.w = __expf(a.w - m);
    b.x = __expf(b.x - m); b.y = __expf(b.y - m);
    b.z = __expf(b.z - m); b.w = __expf(b.w - m);

    float sum = a.x + a.y + a.z + a.w + b.x + b.y + b.z + b.w;
    red[t] = sum;
    __syncthreads();
#pragma unroll
    for (int s = 128; s > 0; s >>= 1) {
        if (t < s) red[t] += red[t + s];
        __syncthreads();
    }
    const float inv = 1.f / red[0];

    a.x *= inv; a.y *= inv; a.z *= inv; a.w *= inv;
    b.x *= inv; b.y *= inv; b.z *= inv; b.w *= inv;
    p4[t] = a;
    p4[t + 256] = b;
}

// ---------------------------------------------------------------------------
// Launch
// Inputs (metadata order): query, key, value, Wq, Wk, Wv, proj_kernel, proj_bias
// Output: [ out (B*T*O) | attn (B*H*T*T) ]  (fallback if out_size differs)
// ---------------------------------------------------------------------------
extern "C" void kernel_launch(void* const* d_in, const int* in_sizes, int n_in,
                              void* d_out, int out_size)
{
    const float* query = (const float*)d_in[0];
    const float* key   = (const float*)d_in[1];
    const float* value = (const float*)d_in[2];
    const float* Wq    = (const float*)d_in[3];
    const float* Wk    = (const float*)d_in[4];
    const float* Wv    = (const float*)d_in[5];
    const float* pk    = (const float*)d_in[6];
    const float* pb    = (const float*)d_in[7];

    float *qp, *kp, *vp, *mhp, *outs, *attns;
    cudaGetSymbolAddress((void**)&qp,    g_q);
    cudaGetSymbolAddress((void**)&kp,    g_k);
    cudaGetSymbolAddress((void**)&vp,    g_v);
    cudaGetSymbolAddress((void**)&mhp,   g_mh);
    cudaGetSymbolAddress((void**)&outs,  g_out_scratch);
    cudaGetSymbolAddress((void**)&attns, g_attn_scratch);

    const long long outN  = (long long)BB * TT * OO;                // 4194304
    const long long attnN = (long long)BB * HH * TT * TT;           // 134217728

    float* outP  = (float*)d_out;
    float* attnP;
    if ((long long)out_size >= outN + attnN) {
        attnP = outP + outN;                 // concatenated outputs
    } else if ((long long)out_size == attnN) {
        attnP = (float*)d_out;               // attn-only output
        outP  = outs;
    } else {
        attnP = attns;                       // out-only output
    }

    // 1) Q/K/V projections: [B*T, E] = X[B*T, E] @ W.T   (TRANSB=1)
    {
        dim3 grid(EE / 128, (BB * TT) / 128, 1);
        gemm128<1><<<grid, 256>>>(query, EE, 1, 0, 0, Wq, EE, 0, 0,
                                  qp, EE, 0, 0, EE, 1.f, nullptr);
        gemm128<1><<<grid, 256>>>(key,   EE, 1, 0, 0, Wk, EE, 0, 0,
                                  kp, EE, 0, 0, EE, 1.f, nullptr);
        gemm128<1><<<grid, 256>>>(value, EE, 1, 0, 0, Wv, EE, 0, 0,
                                  vp, EE, 0, 0, EE, 1.f, nullptr);
    }

    // 2) logits[b,h,n,m] = (1/sqrt(D)) * q[b,n,h,:] . k[b,m,h,:]
    {
        dim3 grid(TT / 128, TT / 128, BB * HH);
        gemm128<1><<<grid, 256>>>(
            qp, HH * DD, HH, (long long)TT * EE, DD,
            kp, HH * DD,     (long long)TT * EE, DD,
            attnP, TT,       (long long)HH * TT * TT, (long long)TT * TT,
            DD, 0.125f, nullptr);
    }

    // 3) softmax rows (in place on attn output)
    softmax_rows<<<BB * HH * TT, 256>>>(attnP);

    // 4) mh[b,n,h,d] = sum_m attn[b,h,n,m] * v[b,m,h,d]
    {
        dim3 grid(1, TT / 128, BB * HH);
        gemm_av<<<grid, 256>>>(
            attnP, TT, HH, (long long)HH * TT * TT, (long long)TT * TT,
            vp, HH * DD,   (long long)TT * EE, DD,
            mhp, HH * DD,  (long long)TT * EE, DD,
            TT);
    }

    // 5) out[b,n,o] = mh[b,n,:] @ proj_kernel[(h*D+d), o] + bias[o]
    {
        dim3 grid(OO / 128, (BB * TT) / 128, 1);
        gemm128<0><<<grid, 256>>>(mhp, EE, 1, 0, 0, pk, OO, 0, 0,
                                  outP, OO, 0, 0, EE, 1.f, pb);
    }
}

// round 5
// speedup vs baseline: 2.2197x; 1.7330x over previous
#include <cuda_runtime.h>
#include <cuda_bf16.h>
#include <cstdint>

// Problem dims
#define BB 2
#define TT 2048
#define HH 16
#define DD 64
#define EE 1024   // HH*DD
#define OO 1024

// Scratch (device globals)
__device__ float g_q[(size_t)BB * TT * EE];
__device__ float g_k[(size_t)BB * TT * EE];
__device__ float g_v[(size_t)BB * TT * EE];
__device__ float g_mh[(size_t)BB * TT * EE];
__device__ float g_vt[(size_t)BB * TT * EE];          // V transposed: [b][h][d][m]
__device__ float g_pkt[(size_t)EE * OO];              // proj kernel transposed: [o][k]
__device__ float g_out_scratch[(size_t)BB * TT * OO];
__device__ float g_attn_scratch[(size_t)BB * HH * TT * TT];

// ---------------------------------------------------------------------------
// mma.sync m16n8k16 bf16 (baseline PTX, works at compute_103)
// ---------------------------------------------------------------------------
__device__ __forceinline__ void mma16816(float* c, const uint32_t* a, const uint32_t* b) {
    asm volatile(
        "mma.sync.aligned.m16n8k16.row.col.f32.bf16.bf16.f32 "
        "{%0,%1,%2,%3}, {%4,%5,%6,%7}, {%8,%9}, {%0,%1,%2,%3};"
        : "+f"(c[0]), "+f"(c[1]), "+f"(c[2]), "+f"(c[3])
        : "r"(a[0]), "r"(a[1]), "r"(a[2]), "r"(a[3]), "r"(b[0]), "r"(b[1]));
}

// ---------------------------------------------------------------------------
// Tensor-core GEMM via mma.sync: C[M,N] = alpha * A[M,K] * B[N,K]^T (+ bias)
// fp32 inputs split on the fly into bf16 (hi,lo); 3-term compensation.
// CTA tile 256 x NTILE, K-step 32. 256 threads = 8 warps (4m x 2n),
// warp tile 64 x NTILE/2.
// Batched over blockIdx.z: offset = (z/zdiv)*s1 + (z%zdiv)*s2.
// ---------------------------------------------------------------------------
template <int NTILE>
__global__ __launch_bounds__(256, 1) void mma_gemm(
    const float* __restrict__ A, int lda, int zdiv,
    long long sA1, long long sA2,
    const float* __restrict__ Bm, int ldb,
    long long sB1, long long sB2,
    float* __restrict__ C, int ldc,
    long long sC1, long long sC2,
    int K, float alpha, const float* __restrict__ bias)
{
    constexpr int KS   = 32;           // k per stage (bf16)
    constexpr int WROW = 20;           // 32-bit words per smem row (40 bf16, padded)
    constexpr int NI   = NTILE / 16;   // 8 or 4 n-fragments per warp
    constexpr int NLOOP = (2048 + NTILE * 8) / 256;  // staging float4 groups / thread

    extern __shared__ char smem[];
    uint32_t* AwH = (uint32_t*)smem;          // 256*20 words
    uint32_t* AwL = AwH + 256 * WROW;
    uint32_t* BwH = AwL + 256 * WROW;
    uint32_t* BwL = BwH + NTILE * WROW;

    const int z = blockIdx.z;
    const int z1 = z / zdiv, z2 = z % zdiv;
    A  += (long long)z1 * sA1 + (long long)z2 * sA2;
    Bm += (long long)z1 * sB1 + (long long)z2 * sB2;
    C  += (long long)z1 * sC1 + (long long)z2 * sC2;

    const int m0 = blockIdx.y * 256;
    const int n0 = blockIdx.x * NTILE;

    const int tid  = threadIdx.x;
    const int warp = tid >> 5;
    const int lane = tid & 31;
    const int wm   = warp & 3;   // 0..3 (m)
    const int wn   = warp >> 2;  // 0..1 (n)
    const int g    = lane >> 2;  // 0..7
    const int tg   = lane & 3;   // 0..3

    float acc[4][NI][4];
#pragma unroll
    for (int mi = 0; mi < 4; mi++)
#pragma unroll
        for (int ni = 0; ni < NI; ni++)
#pragma unroll
            for (int r = 0; r < 4; r++) acc[mi][ni][r] = 0.f;

    for (int kb = 0; kb < K; kb += KS) {
        __syncthreads();   // protect smem from previous iteration's readers
        // ---- stage + split fp32 -> bf16 hi/lo ----
#pragma unroll
        for (int i = 0; i < NLOOP; i++) {
            const int idx = tid + i * 256;
            const bool isA = idx < 2048;
            const int r = isA ? (idx >> 3) : ((idx - 2048) >> 3);
            const int c = (idx & 7) * 4;
            const float* src = isA
                ? &A[(long long)(m0 + r) * lda + kb + c]
                : &Bm[(long long)(n0 + r) * ldb + kb + c];
            float4 x = *(const float4*)src;
            __nv_bfloat162 h0 = __floats2bfloat162_rn(x.x, x.y);
            __nv_bfloat162 h1 = __floats2bfloat162_rn(x.z, x.w);
            float l0 = x.x - __bfloat162float(h0.x);
            float l1 = x.y - __bfloat162float(h0.y);
            float l2 = x.z - __bfloat162float(h1.x);
            float l3 = x.w - __bfloat162float(h1.y);
            __nv_bfloat162 lo0 = __floats2bfloat162_rn(l0, l1);
            __nv_bfloat162 lo1 = __floats2bfloat162_rn(l2, l3);
            const uint32_t w = r * WROW + (c >> 1);
            uint32_t* dh = (isA ? AwH : BwH) + w;
            uint32_t* dl = (isA ? AwL : BwL) + w;
            *(uint2*)dh = make_uint2(*(uint32_t*)&h0, *(uint32_t*)&h1);
            *(uint2*)dl = make_uint2(*(uint32_t*)&lo0, *(uint32_t*)&lo1);
        }
        __syncthreads();

        // ---- MMA over two k16 chunks ----
#pragma unroll
        for (int kk2 = 0; kk2 < 2; kk2++) {
            uint32_t bh[NI][2], bl[NI][2];
#pragma unroll
            for (int ni = 0; ni < NI; ni++) {
                const int n = wn * (NI * 8) + ni * 8 + g;
                const uint32_t w = n * WROW + kk2 * 8 + tg;
                bh[ni][0] = BwH[w];     bh[ni][1] = BwH[w + 4];
                bl[ni][0] = BwL[w];     bl[ni][1] = BwL[w + 4];
            }
#pragma unroll
            for (int mi = 0; mi < 4; mi++) {
                const int r = wm * 64 + mi * 16 + g;
                const uint32_t w = r * WROW + kk2 * 8 + tg;
                uint32_t ah[4] = {AwH[w], AwH[w + 8 * WROW], AwH[w + 4], AwH[w + 8 * WROW + 4]};
                uint32_t al[4] = {AwL[w], AwL[w + 8 * WROW], AwL[w + 4], AwL[w + 8 * WROW + 4]};
#pragma unroll
                for (int ni = 0; ni < NI; ni++) {
                    mma16816(acc[mi][ni], ah, bh[ni]);
                    mma16816(acc[mi][ni], ah, bl[ni]);
                    mma16816(acc[mi][ni], al, bh[ni]);
                }
            }
        }
    }

    // ---- epilogue ----
#pragma unroll
    for (int mi = 0; mi < 4; mi++) {
        const int r0 = m0 + wm * 64 + mi * 16 + g;
        const int r1 = r0 + 8;
#pragma unroll
        for (int ni = 0; ni < NI; ni++) {
            const int c = n0 + wn * (NI * 8) + ni * 8 + tg * 2;
            float2 bv = make_float2(0.f, 0.f);
            if (bias) bv = *(const float2*)&bias[c];
            float2 o0, o1;
            o0.x = acc[mi][ni][0] * alpha + bv.x;
            o0.y = acc[mi][ni][1] * alpha + bv.y;
            o1.x = acc[mi][ni][2] * alpha + bv.x;
            o1.y = acc[mi][ni][3] * alpha + bv.y;
            *(float2*)&C[(long long)r0 * ldc + c] = o0;
            *(float2*)&C[(long long)r1 * ldc + c] = o1;
        }
    }
}

// ---------------------------------------------------------------------------
// Transposes
// ---------------------------------------------------------------------------
__global__ __launch_bounds__(256) void transpose_v(const float* __restrict__ v,
                                                   float* __restrict__ vt)
{
    __shared__ float tile[32][33];
    const int z = blockIdx.z;          // b*HH + h
    const int b = z / HH, h = z % HH;
    const int m0 = blockIdx.x * 32;
    const int d0 = blockIdx.y * 32;
    const int tx = threadIdx.x & 31;
    const int ty0 = threadIdx.x >> 5;
#pragma unroll
    for (int ty = ty0; ty < 32; ty += 8)
        tile[ty][tx] = v[((long long)b * TT + m0 + ty) * EE + h * DD + d0 + tx];
    __syncthreads();
#pragma unroll
    for (int ty = ty0; ty < 32; ty += 8)
        vt[(((long long)z) * DD + d0 + ty) * TT + m0 + tx] = tile[tx][ty];
}

__global__ __launch_bounds__(256) void transpose_pk(const float* __restrict__ pk,
                                                    float* __restrict__ pkt)
{
    __shared__ float tile[32][33];
    const int k0 = blockIdx.x * 32;
    const int o0 = blockIdx.y * 32;
    const int tx = threadIdx.x & 31;
    const int ty0 = threadIdx.x >> 5;
#pragma unroll
    for (int ty = ty0; ty < 32; ty += 8)
        tile[ty][tx] = pk[(long long)(k0 + ty) * OO + o0 + tx];
    __syncthreads();
#pragma unroll
    for (int ty = ty0; ty < 32; ty += 8)
        pkt[(long long)(o0 + ty) * EE + k0 + tx] = tile[tx][ty];
}

// ---------------------------------------------------------------------------
// Row softmax, in place. One block (256 threads) per row of length TT=2048.
// ---------------------------------------------------------------------------
__global__ __launch_bounds__(256) void softmax_rows(float* __restrict__ attn)
{
    __shared__ float red[256];
    const long long row = blockIdx.x;
    float4* p4 = (float4*)(attn + row * (long long)TT);
    const int t = threadIdx.x;

    float4 a = p4[t];
    float4 b = p4[t + 256];

    float m = fmaxf(fmaxf(fmaxf(a.x, a.y), fmaxf(a.z, a.w)),
                    fmaxf(fmaxf(b.x, b.y), fmaxf(b.z, b.w)));
    red[t] = m;
    __syncthreads();
#pragma unroll
    for (int s = 128; s > 0; s >>= 1) {
        if (t < s) red[t] = fmaxf(red[t], red[t + s]);
        __syncthreads();
    }
    m = red[0];
    __syncthreads();

    a.x = __expf(a.x - m); a.y = __expf(a.y - m);
    a.z = __expf(a.z - m); a.w = __expf(a.w - m);
    b.x = __expf(b.x - m); b.y = __expf(b.y - m);
    b.z = __expf(b.z - m); b.w = __expf(b.w - m);

    float sum = a.x + a.y + a.z + a.w + b.x + b.y + b.z + b.w;
    red[t] = sum;
    __syncthreads();
#pragma unroll
    for (int s = 128; s > 0; s >>= 1) {
        if (t < s) red[t] += red[t + s];
        __syncthreads();
    }
    const float inv = 1.f / red[0];

    a.x *= inv; a.y *= inv; a.z *= inv; a.w *= inv;
    b.x *= inv; b.y *= inv; b.z *= inv; b.w *= inv;
    p4[t] = a;
    p4[t + 256] = b;
}

// ---------------------------------------------------------------------------
// Launch
// ---------------------------------------------------------------------------
extern "C" void kernel_launch(void* const* d_in, const int* in_sizes, int n_in,
                              void* d_out, int out_size)
{
    const float* query = (const float*)d_in[0];
    const float* key   = (const float*)d_in[1];
    const float* value = (const float*)d_in[2];
    const float* Wq    = (const float*)d_in[3];
    const float* Wk    = (const float*)d_in[4];
    const float* Wv    = (const float*)d_in[5];
    const float* pk    = (const float*)d_in[6];
    const float* pb    = (const float*)d_in[7];

    float *qp, *kp, *vp, *mhp, *vtp, *pktp, *outs, *attns;
    cudaGetSymbolAddress((void**)&qp,    g_q);
    cudaGetSymbolAddress((void**)&kp,    g_k);
    cudaGetSymbolAddress((void**)&vp,    g_v);
    cudaGetSymbolAddress((void**)&mhp,   g_mh);
    cudaGetSymbolAddress((void**)&vtp,   g_vt);
    cudaGetSymbolAddress((void**)&pktp,  g_pkt);
    cudaGetSymbolAddress((void**)&outs,  g_out_scratch);
    cudaGetSymbolAddress((void**)&attns, g_attn_scratch);

    const long long outN  = (long long)BB * TT * OO;
    const long long attnN = (long long)BB * HH * TT * TT;

    float* outP  = (float*)d_out;
    float* attnP;
    if ((long long)out_size >= outN + attnN) {
        attnP = outP + outN;
    } else if ((long long)out_size == attnN) {
        attnP = (float*)d_out;
        outP  = outs;
    } else {
        attnP = attns;
    }

    // dynamic smem: (256*20 * 2 + NTILE*20 * 2) words * 4B
    constexpr int SMEM128 = (256 * 20 * 2 + 128 * 20 * 2) * 4;   // 61440
    constexpr int SMEM64  = (256 * 20 * 2 + 64 * 20 * 2) * 4;    // 51200
    cudaFuncSetAttribute(mma_gemm<128>, cudaFuncAttributeMaxDynamicSharedMemorySize, SMEM128);
    cudaFuncSetAttribute(mma_gemm<64>,  cudaFuncAttributeMaxDynamicSharedMemorySize, SMEM64);

    // 1) Q/K/V projections: [B*T, E] = X @ W.T
    {
        dim3 grid(EE / 128, (BB * TT) / 256, 1);
        mma_gemm<128><<<grid, 256, SMEM128>>>(query, EE, 1, 0, 0, Wq, EE, 0, 0,
                                              qp, EE, 0, 0, EE, 1.f, nullptr);
        mma_gemm<128><<<grid, 256, SMEM128>>>(key,   EE, 1, 0, 0, Wk, EE, 0, 0,
                                              kp, EE, 0, 0, EE, 1.f, nullptr);
        mma_gemm<128><<<grid, 256, SMEM128>>>(value, EE, 1, 0, 0, Wv, EE, 0, 0,
                                              vp, EE, 0, 0, EE, 1.f, nullptr);
    }

    // transposes: V -> [b][h][d][m], pk -> [o][k]
    {
        dim3 gv(TT / 32, DD / 32, BB * HH);
        transpose_v<<<gv, 256>>>(vp, vtp);
        dim3 gp(EE / 32, OO / 32, 1);
        transpose_pk<<<gp, 256>>>(pk, pktp);
    }

    // 2) logits = 0.125 * q @ k^T (per b,h)
    {
        dim3 grid(TT / 128, TT / 256, BB * HH);
        mma_gemm<128><<<grid, 256, SMEM128>>>(
            qp, EE, HH, (long long)TT * EE, DD,
            kp, EE,     (long long)TT * EE, DD,
            attnP, TT,  (long long)HH * TT * TT, (long long)TT * TT,
            DD, 0.125f, nullptr);
    }

    // 3) softmax
    softmax_rows<<<BB * HH * TT, 256>>>(attnP);

    // 4) mh = attn @ vT^T   (N = 64)
    {
        dim3 grid(1, TT / 256, BB * HH);
        mma_gemm<64><<<grid, 256, SMEM64>>>(
            attnP, TT, HH, (long long)HH * TT * TT, (long long)TT * TT,
            vtp, TT,       (long long)HH * DD * TT, (long long)DD * TT,
            mhp, EE,       (long long)TT * EE, DD,
            TT, 1.f, nullptr);
    }

    // 5) out = mh @ pkT^T + bias
    {
        dim3 grid(OO / 128, (BB * TT) / 256, 1);
        mma_gemm<128><<<grid, 256, SMEM128>>>(mhp, EE, 1, 0, 0, pktp, EE, 0, 0,
                                              outP, OO, 0, 0, EE, 1.f, pb);
    }
}